// round 8
// baseline (speedup 1.0000x reference)
#include <cuda_runtime.h>

// MotionProjector, fused single persistent kernel:
//   out[b,c,v] = sum_{k<7} mask[b,k,v] * (A_bk · g(v) + bvec_bk)_c
//   A = R - I, bvec = t + p - R p, p = weighted centroid of mask over grid.
// grids == meshgrid(linspace(-1,1,64)^3), computed analytically from the index.

namespace {
constexpr int Sd   = 64;
constexpr int VOX  = Sd * Sd * Sd;       // 262144
constexpr int V4   = VOX / 4;            // 65536 float4 per (b,k) slice
constexpr int Bn   = 4;
constexpr int KM   = 7;                  // k = K-1 contributes exactly zero
constexpr int NBK  = Bn * KM;            // 28
constexpr int CHK  = 16;                 // chunks per (b,k) in phase 1
constexpr int NBLK = NBK * CHK;          // 448 blocks (co-resident: 148 SM x 4)
constexpr int THREADS = 256;
constexpr int UNITS = Bn * V4;           // 262144 float4 output columns
}

__device__ float4       g_partials[NBK * CHK];
__device__ unsigned int g_bar;           // reset to 0 by memset node each launch

__device__ __forceinline__ float coordf(int idx) {
    return fmaf((float)idx, 2.0f / 63.0f, -1.0f);
}

__global__ void __launch_bounds__(THREADS, 4)
fused_kernel(const float* __restrict__ mask, const float* __restrict__ trans,
             const float* __restrict__ rot, float* __restrict__ out) {
    const int t  = threadIdx.x;
    const int x  = blockIdx.x;
    const int bk = x >> 4;               // 0..27
    const int chunk = x & 15;
    const int b1 = bk / KM, k1 = bk % KM;

    // ---------------- Phase 1: partial centroid sums (16 float4 / thread) ----
    {
        const float4* __restrict__ m =
            reinterpret_cast<const float4*>(mask) +
            (size_t)(b1 * 8 + k1) * V4 + (size_t)chunk * 4096;

        float s = 0.f, sx = 0.f, sy = 0.f, sz = 0.f;
#pragma unroll
        for (int r = 0; r < 16; ++r) {
            const int q  = r * 256 + t;
            const float4 mv = m[q];
            const int v  = (chunk * 4096 + q) << 2;
            const float gx = coordf(v >> 12);
            const float gy = coordf((v >> 6) & 63);
            const int   l  = v & 63;
            const float ms = (mv.x + mv.y) + (mv.z + mv.w);
            s  += ms;
            sx  = fmaf(ms, gx, sx);
            sy  = fmaf(ms, gy, sy);
            sz += mv.x * coordf(l)     + mv.y * coordf(l + 1)
                + mv.z * coordf(l + 2) + mv.w * coordf(l + 3);
        }
#pragma unroll
        for (int o = 16; o > 0; o >>= 1) {
            s  += __shfl_down_sync(0xffffffffu, s,  o);
            sx += __shfl_down_sync(0xffffffffu, sx, o);
            sy += __shfl_down_sync(0xffffffffu, sy, o);
            sz += __shfl_down_sync(0xffffffffu, sz, o);
        }
        __shared__ float4 red[8];
        const int w = t >> 5, lane = t & 31;
        if (lane == 0) red[w] = make_float4(s, sx, sy, sz);
        __syncthreads();
        if (w == 0) {
            float4 v4 = (lane < 8) ? red[lane] : make_float4(0.f, 0.f, 0.f, 0.f);
            s = v4.x; sx = v4.y; sy = v4.z; sz = v4.w;
#pragma unroll
            for (int o = 4; o > 0; o >>= 1) {
                s  += __shfl_down_sync(0xffffffffu, s,  o);
                sx += __shfl_down_sync(0xffffffffu, sx, o);
                sy += __shfl_down_sync(0xffffffffu, sy, o);
                sz += __shfl_down_sync(0xffffffffu, sz, o);
            }
            if (lane == 0)
                g_partials[bk * CHK + chunk] = make_float4(s, sx, sy, sz);
        }
    }

    // ---------------- Grid barrier (all 448 blocks co-resident) --------------
    __threadfence();
    if (t == 0) {
        atomicAdd(&g_bar, 1u);
        while (*(volatile unsigned int*)&g_bar < (unsigned)NBLK) { }
    }
    __syncthreads();
    __threadfence();

    // ---------------- Coefficients (redundant per block, fixed order) --------
    __shared__ float sc[NBK * 12];
    if (t < NBK) {
        float s = 0.f, sx = 0.f, sy = 0.f, sz = 0.f;
#pragma unroll
        for (int c = 0; c < CHK; ++c) {
            const float4 p = __ldcg(&g_partials[t * CHK + c]);   // L2-fresh
            s += p.x; sx += p.y; sy += p.z; sz += p.w;
        }
        const float px = sx / s, py = sy / s, pz = sz / s;
        const float pv[3] = {px, py, pz};
        const float* __restrict__ R = rot   + (size_t)t * 9;
        const float* __restrict__ T = trans + (size_t)t * 3;
        float* __restrict__ C = sc + t * 12;
#pragma unroll
        for (int r = 0; r < 3; ++r) {
            const float r0 = R[r * 3 + 0], r1 = R[r * 3 + 1], r2 = R[r * 3 + 2];
            C[r * 3 + 0] = r0 - (r == 0 ? 1.f : 0.f);
            C[r * 3 + 1] = r1 - (r == 1 ? 1.f : 0.f);
            C[r * 3 + 2] = r2 - (r == 2 ? 1.f : 0.f);
            C[9 + r]     = T[r] + pv[r] - (r0 * px + r1 * py + r2 * pz);
        }
    }
    __syncthreads();

    // ---------------- Phase 2: apply motion (mask re-read hits L2) -----------
    const float4* __restrict__ mall = reinterpret_cast<const float4*>(mask);
    float4* __restrict__ ob = reinterpret_cast<float4*>(out);

    for (int u = x * THREADS + t; u < UNITS; u += NBLK * THREADS) {
        const int b = u >> 16;
        const int q = u & (V4 - 1);
        const int v = q << 2;
        const float gx  = coordf(v >> 12);
        const float gy  = coordf((v >> 6) & 63);
        const int   l   = v & 63;
        const float gz0 = coordf(l),     gz1 = coordf(l + 1);
        const float gz2 = coordf(l + 2), gz3 = coordf(l + 3);

        float4 a0 = make_float4(0.f, 0.f, 0.f, 0.f);
        float4 a1 = make_float4(0.f, 0.f, 0.f, 0.f);
        float4 a2 = make_float4(0.f, 0.f, 0.f, 0.f);

        const float4* __restrict__ mb = mall + (size_t)b * 8 * V4 + q;
        const float* __restrict__ Cb  = sc + b * KM * 12;

#pragma unroll
        for (int k = 0; k < KM; ++k) {
            const float4 m = mb[(size_t)k * V4];
            const float* __restrict__ C = Cb + k * 12;
            {
                const float com = fmaf(C[0], gx, fmaf(C[1], gy, C[9]));
                const float aa  = C[2];
                a0.x = fmaf(m.x, fmaf(aa, gz0, com), a0.x);
                a0.y = fmaf(m.y, fmaf(aa, gz1, com), a0.y);
                a0.z = fmaf(m.z, fmaf(aa, gz2, com), a0.z);
                a0.w = fmaf(m.w, fmaf(aa, gz3, com), a0.w);
            }
            {
                const float com = fmaf(C[3], gx, fmaf(C[4], gy, C[10]));
                const float aa  = C[5];
                a1.x = fmaf(m.x, fmaf(aa, gz0, com), a1.x);
                a1.y = fmaf(m.y, fmaf(aa, gz1, com), a1.y);
                a1.z = fmaf(m.z, fmaf(aa, gz2, com), a1.z);
                a1.w = fmaf(m.w, fmaf(aa, gz3, com), a1.w);
            }
            {
                const float com = fmaf(C[6], gx, fmaf(C[7], gy, C[11]));
                const float aa  = C[8];
                a2.x = fmaf(m.x, fmaf(aa, gz0, com), a2.x);
                a2.y = fmaf(m.y, fmaf(aa, gz1, com), a2.y);
                a2.z = fmaf(m.z, fmaf(aa, gz2, com), a2.z);
                a2.w = fmaf(m.w, fmaf(aa, gz3, com), a2.w);
            }
        }

        ob[(size_t)(b * 3 + 0) * V4 + q] = a0;
        ob[(size_t)(b * 3 + 1) * V4 + q] = a1;
        ob[(size_t)(b * 3 + 2) * V4 + q] = a2;
    }
}

// ---------------------------------------------------------------------------
extern "C" void kernel_launch(void* const* d_in, const int* in_sizes, int n_in,
                              void* d_out, int out_size) {
    const float* mask  = (const float*)d_in[0];   // (4, 8, 64, 64, 64)
    const float* trans = (const float*)d_in[1];   // (4, 7, 3)
    const float* rot   = (const float*)d_in[2];   // (4, 7, 3, 3)
    // d_in[3] = grids — recomputed analytically, never read.
    float* out = (float*)d_out;                   // (4, 3, 64, 64, 64)

    static void* bar_ptr = nullptr;
    if (!bar_ptr) cudaGetSymbolAddress(&bar_ptr, g_bar);
    cudaMemsetAsync(bar_ptr, 0, sizeof(unsigned int));   // graph memset node

    fused_kernel<<<NBLK, THREADS>>>(mask, trans, rot, out);
}

// round 9
// speedup vs baseline: 1.4935x; 1.4935x over previous
#include <cuda_runtime.h>

// MotionProjector:
//   out[b,c,v] = sum_{k<7} mask[b,k,v] * (A_bk · g(v) + bvec_bk)_c
//   A = R - I, bvec = t + p - R p, p = weighted centroid of mask over grid.
// grids == meshgrid(linspace(-1,1,64)^3), computed analytically from the index.
//
// 2 launches:
//   reduce_kernel : grid (64, 4)  — per block: one 1024-float4 voxel chunk,
//                   ALL 7 k slices (28 independent loads/thread, MLP-rich).
//   motion_kernel : grid (256, 4) — folds partials -> coeffs in-block, then
//                   applies the affine motion (mask re-read is L2-hot).

namespace {
constexpr int Sd   = 64;
constexpr int VOX  = Sd * Sd * Sd;       // 262144
constexpr int V4   = VOX / 4;            // 65536 float4 per (b,k) slice
constexpr int Bn   = 4;
constexpr int KM   = 7;                  // k = K-1 contributes exactly zero
constexpr int CHK  = 64;                 // voxel chunks per b in pass 1
}

// partials[(b*KM + k)*CHK + chunk] = (s, sx, sy, sz)
__device__ float4 g_partials[Bn * KM * CHK];

__device__ __forceinline__ float coordf(int idx) {
    return fmaf((float)idx, 2.0f / 63.0f, -1.0f);
}

// ---------------------------------------------------------------------------
// Pass 1: per-(b,chunk) block reduces all 7 k slices at once.
// ---------------------------------------------------------------------------
__global__ void __launch_bounds__(256, 2)
reduce_kernel(const float* __restrict__ mask) {
    const int t     = threadIdx.x;
    const int chunk = blockIdx.x;            // 0..63
    const int b     = blockIdx.y;            // 0..3
    const float4* __restrict__ mb =
        reinterpret_cast<const float4*>(mask) + (size_t)b * 8 * V4 +
        (size_t)chunk * 1024;

    float s[KM], sx[KM], sy[KM], sz[KM];
#pragma unroll
    for (int k = 0; k < KM; ++k) { s[k] = sx[k] = sy[k] = sz[k] = 0.f; }

#pragma unroll
    for (int r = 0; r < 4; ++r) {
        const int q = r * 256 + t;           // float4 index within chunk
        const int v = (chunk * 1024 + q) << 2;
        const float gx  = coordf(v >> 12);
        const float gy  = coordf((v >> 6) & 63);
        const int   l   = v & 63;
        const float gz0 = coordf(l),     gz1 = coordf(l + 1);
        const float gz2 = coordf(l + 2), gz3 = coordf(l + 3);
#pragma unroll
        for (int k = 0; k < KM; ++k) {
            const float4 mv = mb[(size_t)k * V4 + q];
            const float ms = (mv.x + mv.y) + (mv.z + mv.w);
            s[k]  += ms;
            sx[k]  = fmaf(ms, gx, sx[k]);
            sy[k]  = fmaf(ms, gy, sy[k]);
            sz[k]  = fmaf(mv.x, gz0, fmaf(mv.y, gz1,
                     fmaf(mv.z, gz2, fmaf(mv.w, gz3, sz[k]))));
        }
    }

    // warp reduce all 28 scalars
#pragma unroll
    for (int o = 16; o > 0; o >>= 1) {
#pragma unroll
        for (int k = 0; k < KM; ++k) {
            s[k]  += __shfl_down_sync(0xffffffffu, s[k],  o);
            sx[k] += __shfl_down_sync(0xffffffffu, sx[k], o);
            sy[k] += __shfl_down_sync(0xffffffffu, sy[k], o);
            sz[k] += __shfl_down_sync(0xffffffffu, sz[k], o);
        }
    }
    __shared__ float4 red[8][KM];
    const int w = t >> 5, lane = t & 31;
    if (lane == 0) {
#pragma unroll
        for (int k = 0; k < KM; ++k)
            red[w][k] = make_float4(s[k], sx[k], sy[k], sz[k]);
    }
    __syncthreads();
    if (t < KM) {
        float4 a = red[0][t];
#pragma unroll
        for (int ww = 1; ww < 8; ++ww) {
            const float4 p = red[ww][t];
            a.x += p.x; a.y += p.y; a.z += p.z; a.w += p.w;
        }
        g_partials[(b * KM + t) * CHK + chunk] = a;
    }
}

// ---------------------------------------------------------------------------
// Pass 2: fold partials -> coeffs (one warp per k, redundant per block),
// then apply motion.  grid (256, 4), 256 threads.
// ---------------------------------------------------------------------------
__global__ void __launch_bounds__(256)
motion_kernel(const float* __restrict__ mask, const float* __restrict__ trans,
              const float* __restrict__ rot, float* __restrict__ out) {
    const int t = threadIdx.x;
    const int b = blockIdx.y;
    __shared__ float sc[KM * 12];

    if (t < KM * 32) {                       // warps 0..6, one per k
        const int k = t >> 5, lane = t & 31;
        const float4* __restrict__ gp = g_partials + (b * KM + k) * CHK;
        const float4 p0 = gp[2 * lane];
        const float4 p1 = gp[2 * lane + 1];
        float s  = p0.x + p1.x, sx = p0.y + p1.y;
        float sy = p0.z + p1.z, sz = p0.w + p1.w;
#pragma unroll
        for (int o = 16; o > 0; o >>= 1) {
            s  += __shfl_down_sync(0xffffffffu, s,  o);
            sx += __shfl_down_sync(0xffffffffu, sx, o);
            sy += __shfl_down_sync(0xffffffffu, sy, o);
            sz += __shfl_down_sync(0xffffffffu, sz, o);
        }
        if (lane == 0) {
            const float px = sx / s, py = sy / s, pz = sz / s;
            const float pv[3] = {px, py, pz};
            const float* __restrict__ R = rot   + (size_t)(b * KM + k) * 9;
            const float* __restrict__ T = trans + (size_t)(b * KM + k) * 3;
            float* __restrict__ C = sc + k * 12;
#pragma unroll
            for (int r = 0; r < 3; ++r) {
                const float r0 = R[r * 3 + 0], r1 = R[r * 3 + 1], r2 = R[r * 3 + 2];
                C[r * 3 + 0] = r0 - (r == 0 ? 1.f : 0.f);
                C[r * 3 + 1] = r1 - (r == 1 ? 1.f : 0.f);
                C[r * 3 + 2] = r2 - (r == 2 ? 1.f : 0.f);
                C[9 + r]     = T[r] + pv[r] - (r0 * px + r1 * py + r2 * pz);
            }
        }
    }
    __syncthreads();

    const int q = blockIdx.x * 256 + t;      // float4 index in [0, V4)
    const int v = q << 2;
    const float gx  = coordf(v >> 12);
    const float gy  = coordf((v >> 6) & 63);
    const int   l   = v & 63;
    const float gz0 = coordf(l),     gz1 = coordf(l + 1);
    const float gz2 = coordf(l + 2), gz3 = coordf(l + 3);

    float4 a0 = make_float4(0.f, 0.f, 0.f, 0.f);
    float4 a1 = make_float4(0.f, 0.f, 0.f, 0.f);
    float4 a2 = make_float4(0.f, 0.f, 0.f, 0.f);

    const float4* __restrict__ mb =
        reinterpret_cast<const float4*>(mask) + (size_t)b * 8 * V4 + q;

#pragma unroll
    for (int k = 0; k < KM; ++k) {
        const float4 m = mb[(size_t)k * V4];
        const float* __restrict__ C = sc + k * 12;
        {
            const float com = fmaf(C[0], gx, fmaf(C[1], gy, C[9]));
            const float aa  = C[2];
            a0.x = fmaf(m.x, fmaf(aa, gz0, com), a0.x);
            a0.y = fmaf(m.y, fmaf(aa, gz1, com), a0.y);
            a0.z = fmaf(m.z, fmaf(aa, gz2, com), a0.z);
            a0.w = fmaf(m.w, fmaf(aa, gz3, com), a0.w);
        }
        {
            const float com = fmaf(C[3], gx, fmaf(C[4], gy, C[10]));
            const float aa  = C[5];
            a1.x = fmaf(m.x, fmaf(aa, gz0, com), a1.x);
            a1.y = fmaf(m.y, fmaf(aa, gz1, com), a1.y);
            a1.z = fmaf(m.z, fmaf(aa, gz2, com), a1.z);
            a1.w = fmaf(m.w, fmaf(aa, gz3, com), a1.w);
        }
        {
            const float com = fmaf(C[6], gx, fmaf(C[7], gy, C[11]));
            const float aa  = C[8];
            a2.x = fmaf(m.x, fmaf(aa, gz0, com), a2.x);
            a2.y = fmaf(m.y, fmaf(aa, gz1, com), a2.y);
            a2.z = fmaf(m.z, fmaf(aa, gz2, com), a2.z);
            a2.w = fmaf(m.w, fmaf(aa, gz3, com), a2.w);
        }
    }

    float4* __restrict__ ob = reinterpret_cast<float4*>(out);
    ob[(size_t)(b * 3 + 0) * V4 + q] = a0;
    ob[(size_t)(b * 3 + 1) * V4 + q] = a1;
    ob[(size_t)(b * 3 + 2) * V4 + q] = a2;
}

// ---------------------------------------------------------------------------
extern "C" void kernel_launch(void* const* d_in, const int* in_sizes, int n_in,
                              void* d_out, int out_size) {
    const float* mask  = (const float*)d_in[0];   // (4, 8, 64, 64, 64)
    const float* trans = (const float*)d_in[1];   // (4, 7, 3)
    const float* rot   = (const float*)d_in[2];   // (4, 7, 3, 3)
    // d_in[3] = grids — recomputed analytically, never read.
    float* out = (float*)d_out;                   // (4, 3, 64, 64, 64)

    reduce_kernel<<<dim3(CHK, Bn), 256>>>(mask);
    motion_kernel<<<dim3(V4 / 256, Bn), 256>>>(mask, trans, rot, out);
}